// round 12
// baseline (speedup 1.0000x reference)
#include <cuda_runtime.h>
#include <cstdint>

#define BT20   2621440u     // B*20 (elements per head slab)
#define NROWS  131072u

__device__ float g_h[NROWS * 60];   // trunk activations, row-major [B,60]

// ---- packed f32x2 helpers ----
__device__ __forceinline__ unsigned long long pack2(float lo, float hi) {
    unsigned long long r;
    asm("mov.b64 %0, {%1, %2};" : "=l"(r) : "f"(lo), "f"(hi));
    return r;
}
__device__ __forceinline__ void unpack2(unsigned long long v, float &lo, float &hi) {
    asm("mov.b64 {%0, %1}, %2;" : "=f"(lo), "=f"(hi) : "l"(v));
}
__device__ __forceinline__ void fma2(unsigned long long &d, unsigned long long a,
                                     unsigned long long b) {
    asm("fma.rn.f32x2 %0, %1, %2, %0;" : "+l"(d) : "l"(a), "l"(b));
}
__device__ __forceinline__ void add2(unsigned long long &d, unsigned long long a) {
    asm("add.rn.f32x2 %0, %0, %1;" : "+l"(d) : "l"(a));
}
__device__ __forceinline__ unsigned long long f2lo(const float4 &v) { return pack2(v.x, v.y); }
__device__ __forceinline__ unsigned long long f2hi(const float4 &v) { return pack2(v.z, v.w); }

// integer add on the FMA pipe (IMAD); 'one' is runtime-opaque
__device__ __forceinline__ uint32_t addm(uint32_t a, uint32_t b, uint32_t one) {
    uint32_t r;
    asm("mad.lo.u32 %0, %1, %2, %3;" : "=r"(r) : "r"(b), "r"(one), "r"(a));
    return r;
}

// ---- Threefry-2x32-20, key (0,42); returns ~(o0^o1); keep-bit in MSB ----
// (verified bit-exact vs JAX partitionable threefry, rounds 2-11)
__device__ __forceinline__ uint32_t tf_mix(uint32_t x1_init, uint32_t one) {
    const uint32_t ks1 = 42u;
    const uint32_t ks2 = 0x1BD11BDAu ^ 42u;
    uint32_t x1 = x1_init;          // c1 + ks1
    uint32_t x0 = x1;               // round 1 add with x0=0
    x1 = __funnelshift_l(x1, x1, 13) ^ x0;
#define TF_R(r)  { x0 = addm(x0, x1, one); \
                   x1 = __funnelshift_l(x1, x1, (r)); x1 ^= x0; }
    TF_R(15) TF_R(26) TF_R(6)
    x0 += ks1;  x1 = addm(x1, one * (ks2 + 1u), one);
    TF_R(17) TF_R(29) TF_R(16) TF_R(24)
    x0 += ks2;  x1 = addm(x1, one * 2u, one);
    TF_R(13) TF_R(15) TF_R(26) TF_R(6)
    x1 = addm(x1, one * (ks1 + 3u), one);
    TF_R(17) TF_R(29) TF_R(16) TF_R(24)
    x0 += ks1;  x1 = addm(x1, one * (ks2 + 4u), one);
    TF_R(13) TF_R(15) TF_R(26) TF_R(6)
    x0 += ks2;  x1 = addm(x1, one * 5u, one);
#undef TF_R
    return ~(x0 ^ x1);
}

// ================= Kernel 1: trunk h = relu(W1 @ x + b1) -> g_h ============
__global__ __launch_bounds__(64, 10)
void trunk_kernel(const float* __restrict__ x,
                  const float* __restrict__ W1,
                  const float* __restrict__ b1)
{
    __shared__ __align__(16) float sW1[1200];   // [60][20]
    __shared__           float sb1[64];

    const int tid = threadIdx.x;
    for (int i = tid; i < 300; i += 64)
        ((float4*)sW1)[i] = ((const float4*)W1)[i];
    if (tid < 60) sb1[tid] = b1[tid];
    __syncthreads();

    const unsigned b = blockIdx.x * 64u + (unsigned)tid;

    unsigned long long x2[10];
    {
        const float4* xp = (const float4*)(x + (size_t)b * 20);
        #pragma unroll
        for (int i = 0; i < 5; i++) {
            float4 v = xp[i];
            x2[2*i]   = f2lo(v);
            x2[2*i+1] = f2hi(v);
        }
    }

    float4* hp = (float4*)(g_h + (size_t)b * 60);
    #pragma unroll
    for (int i = 0; i < 15; i++) {      // two h components per half-step
        float hv[4];
        #pragma unroll
        for (int j = 0; j < 2; j++) {
            const int r0 = 4*i + 2*j;
            unsigned long long a0 = 0ull, a1 = 0ull, a2 = 0ull, a3 = 0ull;
            const float4* w0 = (const float4*)(sW1 + r0       * 20);
            const float4* w1 = (const float4*)(sW1 + (r0 + 1) * 20);
            #pragma unroll
            for (int d = 0; d < 5; d++) {
                float4 v0 = w0[d], v1 = w1[d];
                fma2(a0, x2[2*d],   f2lo(v0));
                fma2(a2, x2[2*d+1], f2hi(v0));
                fma2(a1, x2[2*d],   f2lo(v1));
                fma2(a3, x2[2*d+1], f2hi(v1));
            }
            add2(a0, a2);
            add2(a1, a3);
            float s0a, s0b, s1a, s1b;
            unpack2(a0, s0a, s0b);
            unpack2(a1, s1a, s1b);
            hv[2*j]   = fmaxf(s0a + s0b + sb1[r0],     0.f);
            hv[2*j+1] = fmaxf(s1a + s1b + sb1[r0 + 1], 0.f);
        }
        hp[i] = make_float4(hv[0], hv[1], hv[2], hv[3]);
    }
}

// ====== Kernel 2: heads — stationary weights (1 column per thread) =========
// grid: (5 column-blocks of 160 cols, 1024 row-blocks of 128 rows)
__global__ __launch_bounds__(160, 3)
void head_kernel(const float* __restrict__ Wh,
                 const float* __restrict__ bh,
                 float* __restrict__ out,
                 uint32_t one)
{
    __shared__ __align__(16) float4 sh[960];   // 64 rows x 15 float4 of h

    const int tid = threadIdx.x;
    const unsigned col = blockIdx.x * 160u + (unsigned)tid;   // 0..799
    const unsigned k   = col / 20u;
    const unsigned o   = col - k * 20u;
    const unsigned cb  = k * BT20 + o;            // flat element base for row 0

    // this column's weights -> 30 f32x2 registers (loaded once)
    unsigned long long w2[30];
    {
        const float4* wp = (const float4*)(Wh + (size_t)col * 60);
        #pragma unroll
        for (int i = 0; i < 15; i++) {
            float4 v = wp[i];
            w2[2*i]   = f2lo(v);
            w2[2*i+1] = f2hi(v);
        }
    }
    const float bias = bh[col];

    const unsigned row0 = blockIdx.y * 128u;

    // RNG pipeline: mask bits for the first row
    uint32_t tcur = tf_mix(cb + row0 * 20u + 42u, one);

    #pragma unroll 1
    for (int tile = 0; tile < 2; tile++) {
        const unsigned rbase = row0 + (unsigned)tile * 64u;
        __syncthreads();                          // protect prev tile reads
        {
            const float4* hg = (const float4*)(g_h + (size_t)rbase * 60);
            for (int i = tid; i < 960; i += 160) sh[i] = hg[i];
        }
        __syncthreads();

        #pragma unroll 2
        for (int r = 0; r < 64; r++) {
            const unsigned row = rbase + (unsigned)r;
            const float4* hr = sh + r * 15;

            // RNG for NEXT row (independent; interleaves with the dot)
            const uint32_t tnext = tf_mix(cb + (row + 1u) * 20u + 42u, one);

            unsigned long long a0 = 0ull, a1 = 0ull, a2 = 0ull, a3 = 0ull;
            #pragma unroll
            for (int d = 0; d < 15; d += 2) {
                float4 v = hr[d];
                fma2(a0, w2[2*d],   f2lo(v));
                fma2(a1, w2[2*d+1], f2hi(v));
                if (d + 1 < 15) {
                    float4 v1 = hr[d+1];
                    fma2(a2, w2[2*d+2], f2lo(v1));
                    fma2(a3, w2[2*d+3], f2hi(v1));
                }
            }
            add2(a0, a2);
            add2(a1, a3);
            add2(a0, a1);
            float p, q;
            unpack2(a0, p, q);
            const float y = fmaxf(p + q + bias, 0.f);

            // keep-multiplier 2.0/0.0 from MSB of tcur
            const float kf = __uint_as_float(
                (uint32_t)((int32_t)tcur >> 31) & 0x40000000u);
            out[cb + row * 20u] = y * kf;

            tcur = tnext;
        }
    }
}

extern "C" void kernel_launch(void* const* d_in, const int* in_sizes, int n_in,
                              void* d_out, int out_size) {
    const float* x  = (const float*)d_in[0];   // [131072, 20]
    const float* W1 = (const float*)d_in[1];   // [60, 20]
    const float* b1 = (const float*)d_in[2];   // [60]
    const float* Wh = (const float*)d_in[3];   // [40, 20, 60]
    const float* bh = (const float*)d_in[4];   // [40, 20]
    float* out = (float*)d_out;                // [40, 131072, 1, 20]

    const int rows = in_sizes[0] / 20;         // 131072
    trunk_kernel<<<rows / 64, 64>>>(x, W1, b1);
    dim3 g2(5, (unsigned)(rows / 128));
    head_kernel<<<g2, 160>>>(Wh, bh, out, 1u);
}

// round 13
// speedup vs baseline: 1.3450x; 1.3450x over previous
#include <cuda_runtime.h>
#include <cstdint>

#define BT20   2621440u     // B*20 (elements per head slab)
#define HALFN  52428800u    // 20*BT20
#define TPB    128

// ---- packed f32x2 helpers ----
__device__ __forceinline__ unsigned long long pack2(float lo, float hi) {
    unsigned long long r;
    asm("mov.b64 %0, {%1, %2};" : "=l"(r) : "f"(lo), "f"(hi));
    return r;
}
__device__ __forceinline__ void unpack2(unsigned long long v, float &lo, float &hi) {
    asm("mov.b64 {%0, %1}, %2;" : "=f"(lo), "=f"(hi) : "l"(v));
}
__device__ __forceinline__ void fma2(unsigned long long &d, unsigned long long a,
                                     unsigned long long b) {
    asm("fma.rn.f32x2 %0, %1, %2, %0;" : "+l"(d) : "l"(a), "l"(b));
}
__device__ __forceinline__ void add2(unsigned long long &d, unsigned long long a) {
    asm("add.rn.f32x2 %0, %0, %1;" : "+l"(d) : "l"(a));
}
__device__ __forceinline__ unsigned long long f2lo(const float4 &v) { return pack2(v.x, v.y); }
__device__ __forceinline__ unsigned long long f2hi(const float4 &v) { return pack2(v.z, v.w); }

// integer add on the FMA pipe (IMAD); 'one' is runtime-opaque
__device__ __forceinline__ uint32_t addm(uint32_t a, uint32_t b, uint32_t one) {
    uint32_t r;
    asm("mad.lo.u32 %0, %1, %2, %3;" : "=r"(r) : "r"(b), "r"(one), "r"(a));
    return r;
}

// ---- Threefry-2x32-20, key (0,42); returns ~(o0^o1); keep-bit in MSB ----
// (verified bit-exact vs JAX partitionable threefry, rounds 2-12)
__device__ __forceinline__ uint32_t tf_mix(uint32_t x1_init, uint32_t one) {
    const uint32_t ks1 = 42u;
    const uint32_t ks2 = 0x1BD11BDAu ^ 42u;
    uint32_t x1 = x1_init;          // c1 + ks1
    uint32_t x0 = x1;               // round 1 add with x0=0
    x1 = __funnelshift_l(x1, x1, 13) ^ x0;
#define TF_R(r)  { x0 = addm(x0, x1, one); \
                   x1 = __funnelshift_l(x1, x1, (r)); x1 ^= x0; }
    TF_R(15) TF_R(26) TF_R(6)
    x0 += ks1;  x1 += ks2 + 1u;
    TF_R(17) TF_R(29) TF_R(16) TF_R(24)
    x0 += ks2;  x1 += 2u;
    TF_R(13) TF_R(15) TF_R(26) TF_R(6)
    x1 += ks1 + 3u;
    TF_R(17) TF_R(29) TF_R(16) TF_R(24)
    x0 += ks1;  x1 += ks2 + 4u;
    TF_R(13) TF_R(15) TF_R(26) TF_R(6)
    x0 += ks2;  x1 += 5u;
#undef TF_R
    return ~(x0 ^ x1);
}

// keep-multiplier 2.0f / 0.0f from mask bit o
__device__ __forceinline__ float keepf(uint32_t m, int o) {
    return __uint_as_float((uint32_t)((int)(m << (31 - o)) >> 31) & 0x40000000u);
}

// ====== fused kernel, warp-specialized: warps 0-1 GEMM, warps 2-3 RNG ======
__global__ __launch_bounds__(TPB, 4)
void fused_ws_kernel(const float* __restrict__ x,
                     const float* __restrict__ W1,
                     const float* __restrict__ b1,
                     const float* __restrict__ Wh,
                     const float* __restrict__ bh,
                     float* __restrict__ out,
                     uint32_t one)
{
    __shared__ __align__(16) float sW1[1200];   // [60][20]
    __shared__           float sb1[64];
    __shared__ __align__(16) float sbh[800];    // [40][20]
    __shared__ __align__(16) float sWhA[1200];  // Wh[k]      [20][60]
    __shared__ __align__(16) float sWhB[1200];  // Wh[k+20]   [20][60]
    __shared__ uint32_t smA[2][64];             // mask ring: head k
    __shared__ uint32_t smB[2][64];             //            head k+20

    const int tid = threadIdx.x;

    for (int i = tid; i < 300; i += TPB)
        ((float4*)sW1)[i] = ((const float4*)W1)[i];
    for (int i = tid; i < 200; i += TPB)
        ((float4*)sbh)[i] = ((const float4*)bh)[i];
    if (tid < 60) sb1[tid] = b1[tid];
    __syncthreads();

    const bool is_gemm = tid < 64;
    const unsigned lane64 = (unsigned)(tid & 63);
    const unsigned b = blockIdx.x * 64u + lane64;        // row owned (per role)
    const unsigned base_b = b * 20u;

    unsigned long long h2[30];                           // GEMM warps only

    if (is_gemm) {
        // ---- trunk: h = relu(W1 @ x + b1), packed as 30 f32x2 regs ----
        unsigned long long x2[10];
        const float4* xp = (const float4*)(x + (size_t)b * 20);
        #pragma unroll
        for (int i = 0; i < 5; i++) {
            float4 v = xp[i];
            x2[2*i]   = f2lo(v);
            x2[2*i+1] = f2hi(v);
        }
        #pragma unroll
        for (int i = 0; i < 30; i++) {
            unsigned long long a0 = 0ull, a1 = 0ull, a2 = 0ull, a3 = 0ull;
            const float4* w0 = (const float4*)(sW1 + (2*i)   * 20);
            const float4* w1 = (const float4*)(sW1 + (2*i+1) * 20);
            #pragma unroll
            for (int d = 0; d < 5; d++) {
                float4 v0 = w0[d], v1 = w1[d];
                fma2(a0, x2[2*d],   f2lo(v0));
                fma2(a2, x2[2*d+1], f2hi(v0));
                fma2(a1, x2[2*d],   f2lo(v1));
                fma2(a3, x2[2*d+1], f2hi(v1));
            }
            add2(a0, a2);
            add2(a1, a3);
            float s0a, s0b, s1a, s1b;
            unpack2(a0, s0a, s0b);
            unpack2(a1, s1a, s1b);
            h2[i] = pack2(fmaxf(s0a + s0b + sb1[2*i],   0.f),
                          fmaxf(s1a + s1b + sb1[2*i+1], 0.f));
        }
    } else {
        // ---- RNG warps: masks for k = 0 into buffer 0 (overlaps trunk) ----
        uint32_t wA = 0u, wB = 0u;
        const uint32_t j0 = base_b + 42u;
        #pragma unroll
        for (int o = 0; o < 20; o++) {
            wA |= (tf_mix(j0 + (unsigned)o,         one) >> 31) << o;
            wB |= (tf_mix(j0 + (unsigned)o + HALFN, one) >> 31) << o;
        }
        smA[0][lane64] = wA;
        smB[0][lane64] = wB;
    }

    for (int k = 0; k < 20; k++) {
        __syncthreads();   // masks(k) visible; previous weights free
        const float4* srcA = (const float4*)(Wh + (size_t)k        * 1200);
        const float4* srcB = (const float4*)(Wh + (size_t)(k + 20) * 1200);
        for (int i = tid; i < 300; i += TPB) {
            ((float4*)sWhA)[i] = srcA[i];
            ((float4*)sWhB)[i] = srcB[i];
        }
        __syncthreads();

        if (is_gemm) {
            const uint32_t mA = smA[k & 1][lane64];
            const uint32_t mB = smB[k & 1][lane64];
            #pragma unroll 1
            for (int oc = 0; oc < 5; oc++) {
                float y0v[4], y1v[4];
                #pragma unroll
                for (int u = 0; u < 4; u++) {
                    const int o = oc * 4 + u;
                    const float4* wA4 = (const float4*)(sWhA + o * 60);
                    const float4* wB4 = (const float4*)(sWhB + o * 60);
                    unsigned long long a0 = 0ull, a0b = 0ull, a1 = 0ull, a1b = 0ull;
                    #pragma unroll
                    for (int d = 0; d < 15; d++) {
                        float4 va = wA4[d];
                        float4 vb = wB4[d];
                        fma2(a0,  f2lo(va), h2[2*d]);
                        fma2(a0b, f2hi(va), h2[2*d+1]);
                        fma2(a1,  f2lo(vb), h2[2*d]);
                        fma2(a1b, f2hi(vb), h2[2*d+1]);
                    }
                    add2(a0, a0b);
                    add2(a1, a1b);
                    float pA, qA, pB, qB;
                    unpack2(a0, pA, qA);
                    unpack2(a1, pB, qB);
                    float accA = (pA + qA) + sbh[k*20 + o];
                    float accB = (pB + qB) + sbh[(k+20)*20 + o];
                    y0v[u] = fmaxf(accA, 0.f) * keepf(mA, o);
                    y1v[u] = fmaxf(accB, 0.f) * keepf(mB, o);
                }
                *(float4*)(out + (size_t)k        * BT20 + base_b + oc * 4) =
                    make_float4(y0v[0], y0v[1], y0v[2], y0v[3]);
                *(float4*)(out + (size_t)(k + 20) * BT20 + base_b + oc * 4) =
                    make_float4(y1v[0], y1v[1], y1v[2], y1v[3]);
            }
        } else if (k < 19) {
            // ---- RNG warps: produce masks for k+1 into the other buffer ----
            uint32_t wA = 0u, wB = 0u;
            const uint32_t jn = (unsigned)(k + 1) * BT20 + base_b + 42u;
            #pragma unroll
            for (int o = 0; o < 20; o++) {
                wA |= (tf_mix(jn + (unsigned)o,         one) >> 31) << o;
                wB |= (tf_mix(jn + (unsigned)o + HALFN, one) >> 31) << o;
            }
            smA[(k + 1) & 1][lane64] = wA;
            smB[(k + 1) & 1][lane64] = wB;
        }
    }
}

extern "C" void kernel_launch(void* const* d_in, const int* in_sizes, int n_in,
                              void* d_out, int out_size) {
    const float* x  = (const float*)d_in[0];   // [131072, 20]
    const float* W1 = (const float*)d_in[1];   // [60, 20]
    const float* b1 = (const float*)d_in[2];   // [60]
    const float* Wh = (const float*)d_in[3];   // [40, 20, 60]
    const float* bh = (const float*)d_in[4];   // [40, 20]
    float* out = (float*)d_out;                // [40, 131072, 1, 20]

    const int rows = in_sizes[0] / 20;         // 131072
    fused_ws_kernel<<<rows / 64, TPB>>>(x, W1, b1, Wh, bh, out, 1u);
}

// round 15
// speedup vs baseline: 1.9119x; 1.4215x over previous
#include <cuda_runtime.h>
#include <cuda_bf16.h>
#include <cstdint>

#define BT20   2621440u     // B*20 (elements per head slab)
#define NCOLS  800

__device__ __nv_bfloat16 g_Bhi[NCOLS * 64];   // Wh hi, K padded 60->64
__device__ __nv_bfloat16 g_Blo[NCOLS * 64];   // Wh lo

// ---- packed f32x2 helpers (trunk) ----
__device__ __forceinline__ unsigned long long pack2(float lo, float hi) {
    unsigned long long r;
    asm("mov.b64 %0, {%1, %2};" : "=l"(r) : "f"(lo), "f"(hi));
    return r;
}
__device__ __forceinline__ void unpack2(unsigned long long v, float &lo, float &hi) {
    asm("mov.b64 {%0, %1}, %2;" : "=f"(lo), "=f"(hi) : "l"(v));
}
__device__ __forceinline__ void fma2(unsigned long long &d, unsigned long long a,
                                     unsigned long long b) {
    asm("fma.rn.f32x2 %0, %1, %2, %0;" : "+l"(d) : "l"(a), "l"(b));
}
__device__ __forceinline__ void add2(unsigned long long &d, unsigned long long a) {
    asm("add.rn.f32x2 %0, %0, %1;" : "+l"(d) : "l"(a));
}
__device__ __forceinline__ unsigned long long f2lo(const float4 &v) { return pack2(v.x, v.y); }
__device__ __forceinline__ unsigned long long f2hi(const float4 &v) { return pack2(v.z, v.w); }

// integer add on the FMA pipe (IMAD); 'one' is runtime-opaque
__device__ __forceinline__ uint32_t addm(uint32_t a, uint32_t b, uint32_t one) {
    uint32_t r;
    asm("mad.lo.u32 %0, %1, %2, %3;" : "=r"(r) : "r"(b), "r"(one), "r"(a));
    return r;
}

// ---- Threefry-2x32-20, key (0,42); returns ~(o0^o1); keep iff MSB set ----
// (verified bit-exact vs JAX partitionable threefry, rounds 2-13)
__device__ __forceinline__ uint32_t tf_mix(uint32_t x1_init, uint32_t one) {
    const uint32_t ks1 = 42u;
    const uint32_t ks2 = 0x1BD11BDAu ^ 42u;
    uint32_t x1 = x1_init;          // c1 + ks1
    uint32_t x0 = x1;               // round 1 add with x0=0
    x1 = __funnelshift_l(x1, x1, 13) ^ x0;
#define TF_R(r)  { x0 = addm(x0, x1, one); \
                   x1 = __funnelshift_l(x1, x1, (r)); x1 ^= x0; }
    TF_R(15) TF_R(26) TF_R(6)
    x0 += ks1;  x1 += ks2 + 1u;
    TF_R(17) TF_R(29) TF_R(16) TF_R(24)
    x0 += ks2;  x1 += 2u;
    TF_R(13) TF_R(15) TF_R(26) TF_R(6)
    x1 += ks1 + 3u;
    TF_R(17) TF_R(29) TF_R(16) TF_R(24)
    x0 += ks1;  x1 += ks2 + 4u;
    TF_R(13) TF_R(15) TF_R(26) TF_R(6)
    x0 += ks2;  x1 += 5u;
#undef TF_R
    return ~(x0 ^ x1);
}
// keep-multiplier 2.0f / 0.0f from MSB of m
__device__ __forceinline__ float kf(uint32_t m) {
    return __uint_as_float((uint32_t)((int32_t)m >> 31) & 0x40000000u);
}

// bf16 mma.sync (sm_80 PTX feature -> fallback HMMA on sm_103)
__device__ __forceinline__ void mma16816(float &c0, float &c1, float &c2, float &c3,
                                         uint32_t a0, uint32_t a1, uint32_t a2,
                                         uint32_t a3, uint32_t b0, uint32_t b1) {
    asm volatile(
        "mma.sync.aligned.m16n8k16.row.col.f32.bf16.bf16.f32 "
        "{%0,%1,%2,%3}, {%4,%5,%6,%7}, {%8,%9}, {%0,%1,%2,%3};"
        : "+f"(c0), "+f"(c1), "+f"(c2), "+f"(c3)
        : "r"(a0), "r"(a1), "r"(a2), "r"(a3), "r"(b0), "r"(b1));
}

// ============ setup: Wh fp32 -> bf16 hi/lo, K padded to 64 ==================
__global__ void conv_kernel(const float* __restrict__ Wh) {
    const int i = blockIdx.x * 256 + threadIdx.x;    // 0..51199
    const int n = i >> 6, c = i & 63;
    const float v = (c < 60) ? Wh[n * 60 + c] : 0.f;
    const __nv_bfloat16 hi = __float2bfloat16(v);
    g_Bhi[i] = hi;
    g_Blo[i] = __float2bfloat16(v - __bfloat162float(hi));
}

// ============ main: trunk + mma.sync heads + fused dropout ==================
__global__ __launch_bounds__(256, 2)
void mma_kernel(const float* __restrict__ x,
                const float* __restrict__ W1,
                const float* __restrict__ b1,
                const float* __restrict__ bh,
                float* __restrict__ out,
                uint32_t one)
{
    __shared__ __align__(16) float sW1[1200];
    __shared__           float sb1[64];
    __shared__ __align__(16) __nv_bfloat16 sAhi[8][16][72];  // per-warp A tiles
    __shared__ __align__(16) __nv_bfloat16 sAlo[8][16][72];

    const int tid  = threadIdx.x;
    const int wid  = tid >> 5;
    const int lane = tid & 31;

    for (int i = tid; i < 300; i += 256)
        ((float4*)sW1)[i] = ((const float4*)W1)[i];
    if (tid < 60) sb1[tid] = b1[tid];
    __syncthreads();

    // ---- trunk: 2 lanes per row; lane computes 30 of 60 h dims (fp32) ----
    {
        const int rloc = lane >> 1;                 // 0..15 within warp
        const int half = lane & 1;
        const unsigned grow = blockIdx.x * 128u + (unsigned)(wid * 16 + rloc);
        unsigned long long x2[10];
        {
            const float4* xp = (const float4*)(x + (size_t)grow * 20);
            #pragma unroll
            for (int i = 0; i < 5; i++) {
                float4 v = xp[i];
                x2[2*i]   = f2lo(v);
                x2[2*i+1] = f2hi(v);
            }
        }
        #pragma unroll
        for (int t = 0; t < 15; t++) {
            const int d0 = half * 30 + 2 * t;
            unsigned long long a0 = 0ull, a1 = 0ull, a2 = 0ull, a3 = 0ull;
            const float4* w0 = (const float4*)(sW1 + d0 * 20);
            const float4* w1 = w0 + 5;
            #pragma unroll
            for (int d = 0; d < 5; d++) {
                float4 v0 = w0[d], v1 = w1[d];
                fma2(a0, x2[2*d],   f2lo(v0));
                fma2(a2, x2[2*d+1], f2hi(v0));
                fma2(a1, x2[2*d],   f2lo(v1));
                fma2(a3, x2[2*d+1], f2hi(v1));
            }
            add2(a0, a2);
            add2(a1, a3);
            float s0a, s0b, s1a, s1b;
            unpack2(a0, s0a, s0b);
            unpack2(a1, s1a, s1b);
            const float h0 = fmaxf(s0a + s0b + sb1[d0],     0.f);
            const float h1 = fmaxf(s1a + s1b + sb1[d0 + 1], 0.f);
            const __nv_bfloat16 h0h = __float2bfloat16(h0);
            const __nv_bfloat16 h1h = __float2bfloat16(h1);
            const __nv_bfloat16 h0l = __float2bfloat16(h0 - __bfloat162float(h0h));
            const __nv_bfloat16 h1l = __float2bfloat16(h1 - __bfloat162float(h1h));
            *(uint32_t*)&sAhi[wid][rloc][d0] =
                (uint32_t)__bfloat16_as_ushort(h0h) |
                ((uint32_t)__bfloat16_as_ushort(h1h) << 16);
            *(uint32_t*)&sAlo[wid][rloc][d0] =
                (uint32_t)__bfloat16_as_ushort(h0l) |
                ((uint32_t)__bfloat16_as_ushort(h1l) << 16);
        }
        if (half == 0) {                            // zero K-pad dims 60..63
            *(uint32_t*)&sAhi[wid][rloc][60] = 0u;
            *(uint32_t*)&sAhi[wid][rloc][62] = 0u;
            *(uint32_t*)&sAlo[wid][rloc][60] = 0u;
            *(uint32_t*)&sAlo[wid][rloc][62] = 0u;
        }
    }
    __syncwarp();

    // ---- load A fragments (m16n8k16 layout), reused for all col-tiles ----
    const int gid = lane >> 2;              // groupID (row within 8)
    const int tig = lane & 3;               // thread-in-group
    uint32_t ahi[16], alo[16];
    #pragma unroll
    for (int ks = 0; ks < 4; ks++) {
        const int kb = ks * 16 + tig * 2;
        ahi[ks*4+0] = *(uint32_t*)&sAhi[wid][gid    ][kb];
        ahi[ks*4+1] = *(uint32_t*)&sAhi[wid][gid + 8][kb];
        ahi[ks*4+2] = *(uint32_t*)&sAhi[wid][gid    ][kb + 8];
        ahi[ks*4+3] = *(uint32_t*)&sAhi[wid][gid + 8][kb + 8];
        alo[ks*4+0] = *(uint32_t*)&sAlo[wid][gid    ][kb];
        alo[ks*4+1] = *(uint32_t*)&sAlo[wid][gid + 8][kb];
        alo[ks*4+2] = *(uint32_t*)&sAlo[wid][gid    ][kb + 8];
        alo[ks*4+3] = *(uint32_t*)&sAlo[wid][gid + 8][kb + 8];
    }

    const unsigned r0g = blockIdx.x * 128u + (unsigned)(wid * 16 + gid);

    // ---- column-tile loop: 100 tiles of 8 columns ----
    #pragma unroll 1
    for (int ct = 0; ct < 100; ct++) {
        const int colbase = ct * 8;
        const int n = colbase + gid;                       // B column
        const uint32_t* bhp = (const uint32_t*)(g_Bhi + n * 64 + tig * 2);
        const uint32_t* blp = (const uint32_t*)(g_Blo + n * 64 + tig * 2);

        float c0 = 0.f, c1 = 0.f, c2 = 0.f, c3 = 0.f;
        #pragma unroll
        for (int ks = 0; ks < 4; ks++) {
            const uint32_t bh0 = bhp[ks * 8];
            const uint32_t bh1 = bhp[ks * 8 + 4];
            const uint32_t bl0 = blp[ks * 8];
            const uint32_t bl1 = blp[ks * 8 + 4];
            mma16816(c0, c1, c2, c3, ahi[ks*4], ahi[ks*4+1], ahi[ks*4+2],
                     ahi[ks*4+3], bh0, bh1);
            mma16816(c0, c1, c2, c3, alo[ks*4], alo[ks*4+1], alo[ks*4+2],
                     alo[ks*4+3], bh0, bh1);
            mma16816(c0, c1, c2, c3, ahi[ks*4], ahi[ks*4+1], ahi[ks*4+2],
                     ahi[ks*4+3], bl0, bl1);
        }

        // ---- RNG for this lane's 4 elements (overlaps HMMA latency) ----
        const int c0l = colbase + tig * 2;      // even; pair never crosses head
        const unsigned kh = (unsigned)c0l / 20u;
        const unsigned o  = (unsigned)c0l - kh * 20u;
        const uint32_t j00 = kh * BT20 + r0g * 20u + o + 42u;
        const uint32_t m00 = tf_mix(j00,        one);
        const uint32_t m01 = tf_mix(j00 + 1u,   one);
        const uint32_t m10 = tf_mix(j00 + 160u, one);
        const uint32_t m11 = tf_mix(j00 + 161u, one);

        // ---- epilogue: bias, relu, mask, store ----
        const float bias0 = __ldg(bh + c0l);
        const float bias1 = __ldg(bh + c0l + 1);
        const float y00 = fmaxf(c0 + bias0, 0.f) * kf(m00);
        const float y01 = fmaxf(c1 + bias1, 0.f) * kf(m01);
        const float y10 = fmaxf(c2 + bias0, 0.f) * kf(m10);
        const float y11 = fmaxf(c3 + bias1, 0.f) * kf(m11);

        const size_t a0off = (size_t)kh * BT20 + (size_t)r0g * 20u + o;
        *(float2*)(out + a0off)        = make_float2(y00, y01);
        *(float2*)(out + a0off + 160u) = make_float2(y10, y11);
    }
}

extern "C" void kernel_launch(void* const* d_in, const int* in_sizes, int n_in,
                              void* d_out, int out_size) {
    const float* x  = (const float*)d_in[0];   // [131072, 20]
    const float* W1 = (const float*)d_in[1];   // [60, 20]
    const float* b1 = (const float*)d_in[2];   // [60]
    const float* Wh = (const float*)d_in[3];   // [40, 20, 60]
    const float* bh = (const float*)d_in[4];   // [40, 20]
    float* out = (float*)d_out;                // [40, 131072, 1, 20]

    const int rows = in_sizes[0] / 20;         // 131072
    conv_kernel<<<200, 256>>>(Wh);
    mma_kernel<<<rows / 128, 256>>>(x, W1, b1, bh, out, 1u);
}

// round 16
// speedup vs baseline: 2.0456x; 1.0699x over previous
#include <cuda_runtime.h>
#include <cuda_bf16.h>
#include <cstdint>

#define BT20   2621440u     // B*20 (elements per head slab)
#define NCOLS  800

// dynamic smem layout (bytes)
#define SM_AHI 0            // 8 warps x 16 rows x 72 bf16
#define SM_ALO 18432
#define SM_B   36864        // 80 cols x 68 words (hi 32 + lo 32 + pad 4)
#define SM_W1  58624
#define SM_B1  63424
#define SMEM_TOTAL 63744

__device__ __nv_bfloat16 g_Bhi[NCOLS * 64];   // Wh hi, K padded 60->64
__device__ __nv_bfloat16 g_Blo[NCOLS * 64];   // Wh lo

// ---- packed f32x2 helpers (trunk) ----
__device__ __forceinline__ unsigned long long pack2(float lo, float hi) {
    unsigned long long r;
    asm("mov.b64 %0, {%1, %2};" : "=l"(r) : "f"(lo), "f"(hi));
    return r;
}
__device__ __forceinline__ void unpack2(unsigned long long v, float &lo, float &hi) {
    asm("mov.b64 {%0, %1}, %2;" : "=f"(lo), "=f"(hi) : "l"(v));
}
__device__ __forceinline__ void fma2(unsigned long long &d, unsigned long long a,
                                     unsigned long long b) {
    asm("fma.rn.f32x2 %0, %1, %2, %0;" : "+l"(d) : "l"(a), "l"(b));
}
__device__ __forceinline__ void add2(unsigned long long &d, unsigned long long a) {
    asm("add.rn.f32x2 %0, %0, %1;" : "+l"(d) : "l"(a));
}
__device__ __forceinline__ unsigned long long f2lo(const float4 &v) { return pack2(v.x, v.y); }
__device__ __forceinline__ unsigned long long f2hi(const float4 &v) { return pack2(v.z, v.w); }

// integer add on the FMA pipe (IMAD); 'one' is runtime-opaque
__device__ __forceinline__ uint32_t addm(uint32_t a, uint32_t b, uint32_t one) {
    uint32_t r;
    asm("mad.lo.u32 %0, %1, %2, %3;" : "=r"(r) : "r"(b), "r"(one), "r"(a));
    return r;
}
__device__ __forceinline__ uint32_t mullo(uint32_t a, uint32_t b) {
    uint32_t r; asm("mul.lo.u32 %0, %1, %2;" : "=r"(r) : "r"(a), "r"(b)); return r;
}
__device__ __forceinline__ uint32_t mulhi_(uint32_t a, uint32_t b) {
    uint32_t r; asm("mul.hi.u32 %0, %1, %2;" : "=r"(r) : "r"(a), "r"(b)); return r;
}

// ---- Threefry-2x32-20, key (0,42); returns ~(o0^o1); keep iff MSB set ----
// 6 rounds use the R5-verified mul-rotate form (fma pipe) for pipe balance.
__device__ __forceinline__ uint32_t tf_mix(uint32_t x1_init, uint32_t one,
                                           uint32_t c17, uint32_t c29,
                                           uint32_t c16, uint32_t c24) {
    const uint32_t ks1 = 42u;
    const uint32_t ks2 = 0x1BD11BDAu ^ 42u;
    uint32_t x1 = x1_init;          // c1 + ks1
    uint32_t x0 = x1;               // round 1 add with x0=0
    x1 = __funnelshift_l(x1, x1, 13) ^ x0;
#define TF_R(r)  { x0 = addm(x0, x1, one); \
                   x1 = __funnelshift_l(x1, x1, (r)); x1 ^= x0; }
#define TF_M(cc) { x0 = addm(x0, x1, one); \
                   x1 = (mullo(x1, cc) | mulhi_(x1, cc)) ^ x0; }
    TF_R(15) TF_R(26) TF_R(6)
    x0 += ks1;  x1 += ks2 + 1u;
    TF_M(c17) TF_M(c29) TF_M(c16) TF_M(c24)
    x0 += ks2;  x1 += 2u;
    TF_R(13) TF_R(15) TF_R(26) TF_R(6)
    x1 += ks1 + 3u;
    TF_M(c17) TF_M(c29) TF_R(16) TF_R(24)
    x0 += ks1;  x1 += ks2 + 4u;
    TF_R(13) TF_R(15) TF_R(26) TF_R(6)
    x0 += ks2;  x1 += 5u;
#undef TF_R
#undef TF_M
    return ~(x0 ^ x1);
}
// keep-multiplier 2.0f / 0.0f from MSB of m
__device__ __forceinline__ float kf(uint32_t m) {
    return __uint_as_float((uint32_t)((int32_t)m >> 31) & 0x40000000u);
}

// bf16 mma.sync (sm_80 PTX feature -> HMMA on sm_103)
__device__ __forceinline__ void mma16816(float &c0, float &c1, float &c2, float &c3,
                                         uint32_t a0, uint32_t a1, uint32_t a2,
                                         uint32_t a3, uint32_t b0, uint32_t b1) {
    asm volatile(
        "mma.sync.aligned.m16n8k16.row.col.f32.bf16.bf16.f32 "
        "{%0,%1,%2,%3}, {%4,%5,%6,%7}, {%8,%9}, {%0,%1,%2,%3};"
        : "+f"(c0), "+f"(c1), "+f"(c2), "+f"(c3)
        : "r"(a0), "r"(a1), "r"(a2), "r"(a3), "r"(b0), "r"(b1));
}

// ============ setup: Wh fp32 -> bf16 hi/lo, K padded to 64 ==================
__global__ void conv_kernel(const float* __restrict__ Wh) {
    const int i = blockIdx.x * 256 + threadIdx.x;    // 0..51199
    const int n = i >> 6, c = i & 63;
    const float v = (c < 60) ? Wh[n * 60 + c] : 0.f;
    const __nv_bfloat16 hi = __float2bfloat16(v);
    g_Bhi[i] = hi;
    g_Blo[i] = __float2bfloat16(v - __bfloat162float(hi));
}

// ============ main: trunk + mma.sync heads + fused dropout ==================
__global__ __launch_bounds__(256, 3)
void mma_kernel(const float* __restrict__ x,
                const float* __restrict__ W1,
                const float* __restrict__ b1,
                const float* __restrict__ bh,
                float* __restrict__ out,
                uint32_t one)
{
    extern __shared__ char smem[];
    float* sW1 = (float*)(smem + SM_W1);
    float* sb1 = (float*)(smem + SM_B1);

    const int tid  = threadIdx.x;
    const int wid  = tid >> 5;
    const int lane = tid & 31;
    const uint32_t c17 = one << 17, c29 = one << 29;
    const uint32_t c16 = one << 16, c24 = one << 24;

    for (int i = tid; i < 300; i += 256)
        ((float4*)sW1)[i] = ((const float4*)W1)[i];
    if (tid < 60) sb1[tid] = b1[tid];
    __syncthreads();

    // ---- trunk: 2 lanes per row; lane computes 30 of 60 h dims (fp32) ----
    {
        const int rloc = lane >> 1;
        const int half = lane & 1;
        const unsigned grow = blockIdx.x * 128u + (unsigned)(wid * 16 + rloc);
        char* arow_hi = smem + SM_AHI + (wid * 16 + rloc) * 144;
        char* arow_lo = smem + SM_ALO + (wid * 16 + rloc) * 144;
        unsigned long long x2[10];
        {
            const float4* xp = (const float4*)(x + (size_t)grow * 20);
            #pragma unroll
            for (int i = 0; i < 5; i++) {
                float4 v = xp[i];
                x2[2*i]   = f2lo(v);
                x2[2*i+1] = f2hi(v);
            }
        }
        #pragma unroll
        for (int t = 0; t < 15; t++) {
            const int d0 = half * 30 + 2 * t;
            unsigned long long a0 = 0ull, a1 = 0ull, a2 = 0ull, a3 = 0ull;
            const float4* w0 = (const float4*)(sW1 + d0 * 20);
            const float4* w1 = w0 + 5;
            #pragma unroll
            for (int d = 0; d < 5; d++) {
                float4 v0 = w0[d], v1 = w1[d];
                fma2(a0, x2[2*d],   f2lo(v0));
                fma2(a2, x2[2*d+1], f2hi(v0));
                fma2(a1, x2[2*d],   f2lo(v1));
                fma2(a3, x2[2*d+1], f2hi(v1));
            }
            add2(a0, a2);
            add2(a1, a3);
            float s0a, s0b, s1a, s1b;
            unpack2(a0, s0a, s0b);
            unpack2(a1, s1a, s1b);
            const float h0 = fmaxf(s0a + s0b + sb1[d0],     0.f);
            const float h1 = fmaxf(s1a + s1b + sb1[d0 + 1], 0.f);
            const __nv_bfloat16 h0h = __float2bfloat16(h0);
            const __nv_bfloat16 h1h = __float2bfloat16(h1);
            const __nv_bfloat16 h0l = __float2bfloat16(h0 - __bfloat162float(h0h));
            const __nv_bfloat16 h1l = __float2bfloat16(h1 - __bfloat162float(h1h));
            *(uint32_t*)(arow_hi + d0 * 2) =
                (uint32_t)__bfloat16_as_ushort(h0h) |
                ((uint32_t)__bfloat16_as_ushort(h1h) << 16);
            *(uint32_t*)(arow_lo + d0 * 2) =
                (uint32_t)__bfloat16_as_ushort(h0l) |
                ((uint32_t)__bfloat16_as_ushort(h1l) << 16);
        }
        if (half == 0) {                            // zero K-pad dims 60..63
            *(uint32_t*)(arow_hi + 120) = 0u;
            *(uint32_t*)(arow_hi + 124) = 0u;
            *(uint32_t*)(arow_lo + 120) = 0u;
            *(uint32_t*)(arow_lo + 124) = 0u;
        }
    }
    __syncwarp();

    // ---- load A fragments (m16n8k16 layout), reused for all col-tiles ----
    const int gid = lane >> 2;
    const int tig = lane & 3;
    uint32_t ahi[16], alo[16];
    {
        const char* ab_hi = smem + SM_AHI + (wid * 16 + gid) * 144;
        const char* ab_lo = smem + SM_ALO + (wid * 16 + gid) * 144;
        #pragma unroll
        for (int ks = 0; ks < 4; ks++) {
            const int off = ks * 32 + tig * 4;
            ahi[ks*4+0] = *(const uint32_t*)(ab_hi + off);
            ahi[ks*4+1] = *(const uint32_t*)(ab_hi + 8 * 144 + off);
            ahi[ks*4+2] = *(const uint32_t*)(ab_hi + off + 16);
            ahi[ks*4+3] = *(const uint32_t*)(ab_hi + 8 * 144 + off + 16);
            alo[ks*4+0] = *(const uint32_t*)(ab_lo + off);
            alo[ks*4+1] = *(const uint32_t*)(ab_lo + 8 * 144 + off);
            alo[ks*4+2] = *(const uint32_t*)(ab_lo + off + 16);
            alo[ks*4+3] = *(const uint32_t*)(ab_lo + 8 * 144 + off + 16);
        }
    }

    const unsigned r0g = blockIdx.x * 128u + (unsigned)(wid * 16 + gid);

    // ---- chunk loop: 10 chunks of 80 columns, B staged in padded smem ----
    #pragma unroll 1
    for (int ch = 0; ch < 10; ch++) {
        __syncthreads();                    // prev chunk's tiles done
        {
            const uint4* ghi = ((const uint4*)g_Bhi) + (size_t)(ch * 80) * 8;
            const uint4* glo = ((const uint4*)g_Blo) + (size_t)(ch * 80) * 8;
            for (int i = tid; i < 1280; i += 256) {
                const int col = i >> 4, p = i & 15;
                if (p < 8)
                    *(uint4*)(smem + SM_B + (col * 68 + p * 4) * 4) =
                        ghi[col * 8 + p];
                else
                    *(uint4*)(smem + SM_B + (col * 68 + 32 + (p - 8) * 4) * 4) =
                        glo[col * 8 + (p - 8)];
            }
        }
        __syncthreads();

        #pragma unroll 1
        for (int tt = 0; tt < 10; tt++) {
            const int colbase = ch * 80 + tt * 8;
            const char* bcol = smem + SM_B + (size_t)(tt * 8 + gid) * 272;

            float c0 = 0.f, c1 = 0.f, c2 = 0.f, c3 = 0.f;
            #pragma unroll
            for (int ks = 0; ks < 4; ks++) {
                const int wo = (ks * 8 + tig) * 4;
                const uint32_t bh0 = *(const uint32_t*)(bcol + wo);
                const uint32_t bh1 = *(const uint32_t*)(bcol + wo + 16);
                const uint32_t bl0 = *(const uint32_t*)(bcol + 128 + wo);
                const uint32_t bl1 = *(const uint32_t*)(bcol + 128 + wo + 16);
                mma16816(c0, c1, c2, c3, ahi[ks*4], ahi[ks*4+1], ahi[ks*4+2],
                         ahi[ks*4+3], bh0, bh1);
                mma16816(c0, c1, c2, c3, alo[ks*4], alo[ks*4+1], alo[ks*4+2],
                         alo[ks*4+3], bh0, bh1);
                mma16816(c0, c1, c2, c3, ahi[ks*4], ahi[ks*4+1], ahi[ks*4+2],
                         ahi[ks*4+3], bl0, bl1);
            }

            // ---- RNG for this lane's 4 elements (overlaps HMMA latency) ----
            const int c0l = colbase + tig * 2;      // even; never crosses a head
            const unsigned kh = (unsigned)c0l / 20u;
            const unsigned o  = (unsigned)c0l - kh * 20u;
            const uint32_t j00 = kh * BT20 + r0g * 20u + o + 42u;
            const uint32_t m00 = tf_mix(j00,        one, c17, c29, c16, c24);
            const uint32_t m01 = tf_mix(j00 + 1u,   one, c17, c29, c16, c24);
            const uint32_t m10 = tf_mix(j00 + 160u, one, c17, c29, c16, c24);
            const uint32_t m11 = tf_mix(j00 + 161u, one, c17, c29, c16, c24);

            // ---- epilogue: bias, relu, mask, store ----
            const float bias0 = __ldg(bh + c0l);
            const float bias1 = __ldg(bh + c0l + 1);
            const float y00 = fmaxf(c0 + bias0, 0.f) * kf(m00);
            const float y01 = fmaxf(c1 + bias1, 0.f) * kf(m01);
            const float y10 = fmaxf(c2 + bias0, 0.f) * kf(m10);
            const float y11 = fmaxf(c3 + bias1, 0.f) * kf(m11);

            const size_t a0off = (size_t)kh * BT20 + (size_t)r0g * 20u + o;
            *(float2*)(out + a0off)        = make_float2(y00, y01);
            *(float2*)(out + a0off + 160u) = make_float2(y10, y11);
        }
    }
}

extern "C" void kernel_launch(void* const* d_in, const int* in_sizes, int n_in,
                              void* d_out, int out_size) {
    const float* x  = (const float*)d_in[0];   // [131072, 20]
    const float* W1 = (const float*)d_in[1];   // [60, 20]
    const float* b1 = (const float*)d_in[2];   // [60]
    const float* Wh = (const float*)d_in[3];   // [40, 20, 60]
    const float* bh = (const float*)d_in[4];   // [40, 20]
    float* out = (float*)d_out;                // [40, 131072, 1, 20]

    cudaFuncSetAttribute(mma_kernel,
                         cudaFuncAttributeMaxDynamicSharedMemorySize, SMEM_TOTAL);

    const int rows = in_sizes[0] / 20;         // 131072
    conv_kernel<<<200, 256>>>(Wh);
    mma_kernel<<<rows / 128, 256, SMEM_TOTAL>>>(x, W1, b1, bh, out, 1u);
}

// round 17
// speedup vs baseline: 2.1946x; 1.0728x over previous
#include <cuda_runtime.h>
#include <cuda_bf16.h>
#include <cstdint>

#define BT20   2621440u     // B*20 (elements per head slab)
#define NCOLS  800

// dynamic smem layout (bytes)
#define SM_AHI 0            // 8 warps x 16 rows x 72 bf16
#define SM_ALO 18432
#define SM_B   36864        // 80 cols x 68 words (hi 32 + lo 32 + pad 4)
#define SM_W1  58624
#define SM_B1  63424
#define SMEM_TOTAL 63744

__device__ __nv_bfloat16 g_Bhi[NCOLS * 64];   // Wh hi, K padded 60->64
__device__ __nv_bfloat16 g_Blo[NCOLS * 64];   // Wh lo

// ---- packed f32x2 helpers (trunk) ----
__device__ __forceinline__ unsigned long long pack2(float lo, float hi) {
    unsigned long long r;
    asm("mov.b64 %0, {%1, %2};" : "=l"(r) : "f"(lo), "f"(hi));
    return r;
}
__device__ __forceinline__ void unpack2(unsigned long long v, float &lo, float &hi) {
    asm("mov.b64 {%0, %1}, %2;" : "=f"(lo), "=f"(hi) : "l"(v));
}
__device__ __forceinline__ void fma2(unsigned long long &d, unsigned long long a,
                                     unsigned long long b) {
    asm("fma.rn.f32x2 %0, %1, %2, %0;" : "+l"(d) : "l"(a), "l"(b));
}
__device__ __forceinline__ void add2(unsigned long long &d, unsigned long long a) {
    asm("add.rn.f32x2 %0, %0, %1;" : "+l"(d) : "l"(a));
}
__device__ __forceinline__ unsigned long long f2lo(const float4 &v) { return pack2(v.x, v.y); }
__device__ __forceinline__ unsigned long long f2hi(const float4 &v) { return pack2(v.z, v.w); }

// integer add on the FMA pipe (IMAD); 'one' is runtime-opaque
__device__ __forceinline__ uint32_t addm(uint32_t a, uint32_t b, uint32_t one) {
    uint32_t r;
    asm("mad.lo.u32 %0, %1, %2, %3;" : "=r"(r) : "r"(b), "r"(one), "r"(a));
    return r;
}
__device__ __forceinline__ uint32_t mullo(uint32_t a, uint32_t b) {
    uint32_t r; asm("mul.lo.u32 %0, %1, %2;" : "=r"(r) : "r"(a), "r"(b)); return r;
}
__device__ __forceinline__ uint32_t mulhi_(uint32_t a, uint32_t b) {
    uint32_t r; asm("mul.hi.u32 %0, %1, %2;" : "=r"(r) : "r"(a), "r"(b)); return r;
}

// ---- Threefry-2x32-20, key (0,42); returns ~(o0^o1); keep iff MSB set ----
// Pipe-balanced: 4 mul-rotate rounds + all key injections on the fma pipe
// (IMAD); remaining rounds funnel-shift on alu. Same verified bitstream.
__device__ __forceinline__ uint32_t tf_mix(uint32_t x1_init, uint32_t one,
                                           uint32_t c17, uint32_t c29,
                                           uint32_t c16, uint32_t c24) {
    const uint32_t ks1 = 42u;
    const uint32_t ks2 = 0x1BD11BDAu ^ 42u;
    uint32_t x1 = x1_init;          // c1 + ks1
    uint32_t x0 = x1;               // round 1 add with x0=0
    x1 = __funnelshift_l(x1, x1, 13) ^ x0;
#define TF_R(r)  { x0 = addm(x0, x1, one); \
                   x1 = __funnelshift_l(x1, x1, (r)); x1 ^= x0; }
#define TF_M(cc) { x0 = addm(x0, x1, one); \
                   x1 = (mullo(x1, cc) | mulhi_(x1, cc)) ^ x0; }
    TF_R(15) TF_R(26) TF_R(6)
    x0 = addm(x0, one * ks1, one);        x1 = addm(x1, one * (ks2 + 1u), one);
    TF_M(c17) TF_M(c29) TF_M(c16) TF_M(c24)
    x0 = addm(x0, one * ks2, one);        x1 = addm(x1, one * 2u, one);
    TF_R(13) TF_R(15) TF_R(26) TF_R(6)
    x1 = addm(x1, one * (ks1 + 3u), one);
    TF_R(17) TF_R(29) TF_R(16) TF_R(24)
    x0 = addm(x0, one * ks1, one);        x1 = addm(x1, one * (ks2 + 4u), one);
    TF_R(13) TF_R(15) TF_R(26) TF_R(6)
    x0 = addm(x0, one * ks2, one);        x1 = addm(x1, one * 5u, one);
#undef TF_R
#undef TF_M
    return ~(x0 ^ x1);
}
// keep-multiplier 2.0f / 0.0f from MSB of m
__device__ __forceinline__ float kf(uint32_t m) {
    return __uint_as_float((uint32_t)((int32_t)m >> 31) & 0x40000000u);
}

// bf16 mma.sync (sm_80 PTX feature -> HMMA on sm_103)
__device__ __forceinline__ void mma16816(float &c0, float &c1, float &c2, float &c3,
                                         uint32_t a0, uint32_t a1, uint32_t a2,
                                         uint32_t a3, uint32_t b0, uint32_t b1) {
    asm volatile(
        "mma.sync.aligned.m16n8k16.row.col.f32.bf16.bf16.f32 "
        "{%0,%1,%2,%3}, {%4,%5,%6,%7}, {%8,%9}, {%0,%1,%2,%3};"
        : "+f"(c0), "+f"(c1), "+f"(c2), "+f"(c3)
        : "r"(a0), "r"(a1), "r"(a2), "r"(a3), "r"(b0), "r"(b1));
}

// ============ setup: Wh fp32 -> bf16 hi/lo, K padded to 64 ==================
__global__ void conv_kernel(const float* __restrict__ Wh) {
    const int i = blockIdx.x * 256 + threadIdx.x;    // 0..51199
    const int n = i >> 6, c = i & 63;
    const float v = (c < 60) ? Wh[n * 60 + c] : 0.f;
    const __nv_bfloat16 hi = __float2bfloat16(v);
    g_Bhi[i] = hi;
    g_Blo[i] = __float2bfloat16(v - __bfloat162float(hi));
}

// ============ main: trunk + mma.sync heads + fused dropout ==================
__global__ __launch_bounds__(256, 3)
void mma_kernel(const float* __restrict__ x,
                const float* __restrict__ W1,
                const float* __restrict__ b1,
                const float* __restrict__ bh,
                float* __restrict__ out,
                uint32_t one)
{
    extern __shared__ char smem[];
    float* sW1 = (float*)(smem + SM_W1);
    float* sb1 = (float*)(smem + SM_B1);

    const int tid  = threadIdx.x;
    const int wid  = tid >> 5;
    const int lane = tid & 31;
    const uint32_t c17 = one << 17, c29 = one << 29;
    const uint32_t c16 = one << 16, c24 = one << 24;

    for (int i = tid; i < 300; i += 256)
        ((float4*)sW1)[i] = ((const float4*)W1)[i];
    if (tid < 60) sb1[tid] = b1[tid];
    __syncthreads();

    // ---- trunk: 2 lanes per row; lane computes 30 of 60 h dims (fp32) ----
    {
        const int rloc = lane >> 1;
        const int half = lane & 1;
        const unsigned grow = blockIdx.x * 128u + (unsigned)(wid * 16 + rloc);
        char* arow_hi = smem + SM_AHI + (wid * 16 + rloc) * 144;
        char* arow_lo = smem + SM_ALO + (wid * 16 + rloc) * 144;
        unsigned long long x2[10];
        {
            const float4* xp = (const float4*)(x + (size_t)grow * 20);
            #pragma unroll
            for (int i = 0; i < 5; i++) {
                float4 v = xp[i];
                x2[2*i]   = f2lo(v);
                x2[2*i+1] = f2hi(v);
            }
        }
        #pragma unroll
        for (int t = 0; t < 15; t++) {
            const int d0 = half * 30 + 2 * t;
            unsigned long long a0 = 0ull, a1 = 0ull, a2 = 0ull, a3 = 0ull;
            const float4* w0 = (const float4*)(sW1 + d0 * 20);
            const float4* w1 = w0 + 5;
            #pragma unroll
            for (int d = 0; d < 5; d++) {
                float4 v0 = w0[d], v1 = w1[d];
                fma2(a0, x2[2*d],   f2lo(v0));
                fma2(a2, x2[2*d+1], f2hi(v0));
                fma2(a1, x2[2*d],   f2lo(v1));
                fma2(a3, x2[2*d+1], f2hi(v1));
            }
            add2(a0, a2);
            add2(a1, a3);
            float s0a, s0b, s1a, s1b;
            unpack2(a0, s0a, s0b);
            unpack2(a1, s1a, s1b);
            const float h0 = fmaxf(s0a + s0b + sb1[d0],     0.f);
            const float h1 = fmaxf(s1a + s1b + sb1[d0 + 1], 0.f);
            const __nv_bfloat16 h0h = __float2bfloat16(h0);
            const __nv_bfloat16 h1h = __float2bfloat16(h1);
            const __nv_bfloat16 h0l = __float2bfloat16(h0 - __bfloat162float(h0h));
            const __nv_bfloat16 h1l = __float2bfloat16(h1 - __bfloat162float(h1h));
            *(uint32_t*)(arow_hi + d0 * 2) =
                (uint32_t)__bfloat16_as_ushort(h0h) |
                ((uint32_t)__bfloat16_as_ushort(h1h) << 16);
            *(uint32_t*)(arow_lo + d0 * 2) =
                (uint32_t)__bfloat16_as_ushort(h0l) |
                ((uint32_t)__bfloat16_as_ushort(h1l) << 16);
        }
        if (half == 0) {                            // zero K-pad dims 60..63
            *(uint32_t*)(arow_hi + 120) = 0u;
            *(uint32_t*)(arow_hi + 124) = 0u;
            *(uint32_t*)(arow_lo + 120) = 0u;
            *(uint32_t*)(arow_lo + 124) = 0u;
        }
    }
    __syncwarp();

    // ---- load A fragments (m16n8k16 layout), reused for all col-tiles ----
    const int gid = lane >> 2;
    const int tig = lane & 3;
    uint32_t ahi[16], alo[16];
    {
        const char* ab_hi = smem + SM_AHI + (wid * 16 + gid) * 144;
        const char* ab_lo = smem + SM_ALO + (wid * 16 + gid) * 144;
        #pragma unroll
        for (int ks = 0; ks < 4; ks++) {
            const int off = ks * 32 + tig * 4;
            ahi[ks*4+0] = *(const uint32_t*)(ab_hi + off);
            ahi[ks*4+1] = *(const uint32_t*)(ab_hi + 8 * 144 + off);
            ahi[ks*4+2] = *(const uint32_t*)(ab_hi + off + 16);
            ahi[ks*4+3] = *(const uint32_t*)(ab_hi + 8 * 144 + off + 16);
            alo[ks*4+0] = *(const uint32_t*)(ab_lo + off);
            alo[ks*4+1] = *(const uint32_t*)(ab_lo + 8 * 144 + off);
            alo[ks*4+2] = *(const uint32_t*)(ab_lo + off + 16);
            alo[ks*4+3] = *(const uint32_t*)(ab_lo + 8 * 144 + off + 16);
        }
    }

    const unsigned r0g = blockIdx.x * 128u + (unsigned)(wid * 16 + gid);

    // ---- chunk loop: 10 chunks of 80 columns, B staged in padded smem ----
    #pragma unroll 1
    for (int ch = 0; ch < 10; ch++) {
        __syncthreads();                    // prev chunk's tiles done
        {
            const uint4* ghi = ((const uint4*)g_Bhi) + (size_t)(ch * 80) * 8;
            const uint4* glo = ((const uint4*)g_Blo) + (size_t)(ch * 80) * 8;
            for (int i = tid; i < 1280; i += 256) {
                const int col = i >> 4, p = i & 15;
                if (p < 8)
                    *(uint4*)(smem + SM_B + (col * 68 + p * 4) * 4) =
                        ghi[col * 8 + p];
                else
                    *(uint4*)(smem + SM_B + (col * 68 + 32 + (p - 8) * 4) * 4) =
                        glo[col * 8 + (p - 8)];
            }
        }
        __syncthreads();

        #pragma unroll 1
        for (int tt = 0; tt < 10; tt++) {
            const int colbase = ch * 80 + tt * 8;
            const char* bcol = smem + SM_B + (size_t)(tt * 8 + gid) * 272;

            float c0 = 0.f, c1 = 0.f, c2 = 0.f, c3 = 0.f;
            #pragma unroll
            for (int ks = 0; ks < 4; ks++) {
                const int wo = (ks * 8 + tig) * 4;
                const uint32_t bh0 = *(const uint32_t*)(bcol + wo);
                const uint32_t bh1 = *(const uint32_t*)(bcol + wo + 16);
                const uint32_t bl0 = *(const uint32_t*)(bcol + 128 + wo);
                const uint32_t bl1 = *(const uint32_t*)(bcol + 128 + wo + 16);
                mma16816(c0, c1, c2, c3, ahi[ks*4], ahi[ks*4+1], ahi[ks*4+2],
                         ahi[ks*4+3], bh0, bh1);
                mma16816(c0, c1, c2, c3, alo[ks*4], alo[ks*4+1], alo[ks*4+2],
                         alo[ks*4+3], bh0, bh1);
                mma16816(c0, c1, c2, c3, ahi[ks*4], ahi[ks*4+1], ahi[ks*4+2],
                         ahi[ks*4+3], bl0, bl1);
            }

            // ---- RNG for this lane's 4 elements (overlaps HMMA latency) ----
            const int c0l = colbase + tig * 2;      // even; never crosses a head
            const unsigned kh = (unsigned)c0l / 20u;
            const unsigned o  = (unsigned)c0l - kh * 20u;
            const uint32_t j00 = kh * BT20 + r0g * 20u + o + 42u;
            const uint32_t m00 = tf_mix(j00,        one, c17, c29, c16, c24);
            const uint32_t m01 = tf_mix(j00 + 1u,   one, c17, c29, c16, c24);
            const uint32_t m10 = tf_mix(j00 + 160u, one, c17, c29, c16, c24);
            const uint32_t m11 = tf_mix(j00 + 161u, one, c17, c29, c16, c24);

            // ---- epilogue: bias, relu, mask, store ----
            const float bias0 = __ldg(bh + c0l);
            const float bias1 = __ldg(bh + c0l + 1);
            const float y00 = fmaxf(c0 + bias0, 0.f) * kf(m00);
            const float y01 = fmaxf(c1 + bias1, 0.f) * kf(m01);
            const float y10 = fmaxf(c2 + bias0, 0.f) * kf(m10);
            const float y11 = fmaxf(c3 + bias1, 0.f) * kf(m11);

            const size_t a0off = (size_t)kh * BT20 + (size_t)r0g * 20u + o;
            *(float2*)(out + a0off)        = make_float2(y00, y01);
            *(float2*)(out + a0off + 160u) = make_float2(y10, y11);
        }
    }
}

extern "C" void kernel_launch(void* const* d_in, const int* in_sizes, int n_in,
                              void* d_out, int out_size) {
    const float* x  = (const float*)d_in[0];   // [131072, 20]
    const float* W1 = (const float*)d_in[1];   // [60, 20]
    const float* b1 = (const float*)d_in[2];   // [60]
    const float* Wh = (const float*)d_in[3];   // [40, 20, 60]
    const float* bh = (const float*)d_in[4];   // [40, 20]
    float* out = (float*)d_out;                // [40, 131072, 1, 20]

    cudaFuncSetAttribute(mma_kernel,
                         cudaFuncAttributeMaxDynamicSharedMemorySize, SMEM_TOTAL);

    const int rows = in_sizes[0] / 20;         // 131072
    conv_kernel<<<200, 256>>>(Wh);
    mma_kernel<<<rows / 128, 256, SMEM_TOTAL>>>(x, W1, b1, bh, out, 1u);
}